// round 12
// baseline (speedup 1.0000x reference)
#include <cuda_runtime.h>

#define NQ      12
#define DIM     4096
#define THREADS 256
#define EPT     16
#define STSZ    4224        // scalar padded layout: addr = s + (s>>5), max 4222

// tan-form RY butterfly (deferred cosine): a0' = a0 - t*a1 ; a1' = a1 + t*a0
#define REG_BF4T(TT, QBASE)                                                \
    _Pragma("unroll")                                                      \
    for (int rb = 0; rb < 4; rb++) {                                       \
        const float tg = (TT)[(QBASE) + rb];                               \
        _Pragma("unroll")                                                  \
        for (int m = 0; m < 8; m++) {                                      \
            const int low = (1 << rb) - 1;                                 \
            const int j0  = ((m & ~low) << 1) | (m & low);                 \
            const int j1  = j0 | (1 << rb);                                \
            float a0 = v[j0];                                              \
            v[j0] = fmaf(-tg, v[j1], a0);                                  \
            v[j1] = fmaf( tg, a0,   v[j1]);                                \
        }                                                                  \
    }

__global__ __launch_bounds__(THREADS, 6)
void qc_kernel(const float* __restrict__ x,
               const float* __restrict__ th,
               float* __restrict__ out)
{
    __shared__ float st[STSZ];
    __shared__ float enc_c[NQ], enc_s[NQ];
    __shared__ float th_t[2][NQ];
    __shared__ float cosv[2 * NQ];
    __shared__ float red[(THREADS / 32) * NQ];

    const int b    = blockIdx.x;
    const int tid  = threadIdx.x;
    const int lane = tid & 31;

    // padded bases: addr = s + (s>>5) (R4-verified conflict-free for A/B/C)
    const int baseA = tid * 16 + (tid >> 1);                 // + j
    const int baseB = tid + (tid >> 5);                      // + 264*j
    const int tb    = ((tid >> 5) & 1) | (((tid >> 4) & 1) << 1)
                    | (((tid >> 6) & 1) << 2) | (((tid >> 7) & 1) << 3);
    const int baseC = (tid & 15) + 264 * tb;                 // + 16*j + (j>>1)

    // ---- angle precompute across 2 warps ----
    if (tid < NQ) {
        float s_, c_;
        sincosf(0.5f * x[b * NQ + tid], &s_, &c_);
        enc_c[tid] = c_; enc_s[tid] = s_;
    } else if (tid >= 32 && tid < 32 + 2 * NQ) {
        int k = tid - 32;                 // layer*12 + q
        float s_, c_;
        sincosf(0.5f * th[k], &s_, &c_);
        th_t[k / NQ][k % NQ] = s_ / c_;
        cosv[k] = c_;
    }
    __syncthreads();

    // ---- product state in registers (ownership A: s = 16*tid + j) ----
    float v[EPT];
    {
        float h = (tid & 1) ? enc_s[4] : enc_c[4];
        #pragma unroll
        for (int i = 1; i < 8; i++)
            h *= ((tid >> i) & 1) ? enc_s[4 + i] : enc_c[4 + i];
        float lo[4], hi[4];
        #pragma unroll
        for (int m = 0; m < 4; m++) {
            lo[m] = ((m & 1) ? enc_s[0] : enc_c[0]) * ((m & 2) ? enc_s[1] : enc_c[1]);
            hi[m] = ((m & 1) ? enc_s[2] : enc_c[2]) * ((m & 2) ? enc_s[3] : enc_c[3]);
        }
        #pragma unroll
        for (int j = 0; j < EPT; j++)
            v[j] = h * lo[j & 3] * hi[j >> 2];
    }

    // ---- variational layers (tan-form gates, cosines deferred) ----
    #pragma unroll
    for (int layer = 0; layer < 2; layer++) {
        const float* T = th_t[layer];

        REG_BF4T(T, 0)                          // qubits 0-3 (A)

        #pragma unroll
        for (int j = 0; j < EPT; j++) st[baseA + j] = v[j];
        __syncthreads();
        #pragma unroll
        for (int j = 0; j < EPT; j++) v[j] = st[baseC + 16 * j + (j >> 1)];

        REG_BF4T(T, 4)                          // qubits 4-7 (C)

        #pragma unroll
        for (int j = 0; j < EPT; j++) st[baseC + 16 * j + (j >> 1)] = v[j];
        __syncthreads();
        #pragma unroll
        for (int j = 0; j < EPT; j++) v[j] = st[baseB + 264 * j];

        REG_BF4T(T, 8)                          // qubits 8-11 (B)

        if (layer == 0) {
            // CNOT ring = bit-linear permutation; scatter B -> gather A
            unsigned px = tid; px ^= px << 1; px ^= px << 2; px ^= px << 4;
            const int Pt  = (px >> 7) & 1;
            const int Tt  = (tid ^ (int)(px << 1)) & 0xFE;
            const int t0p = (tid & 1) ^ Pt;
            const int pb0 = Tt + t0p       + (Tt >> 5);
            const int pb1 = Tt + (t0p ^ 1) + (Tt >> 5);
            const int msk = Pt ? 15 : 0;

            __syncthreads();                    // all B reads done before scatter
            #pragma unroll
            for (int j = 0; j < EPT; j++) {
                const int j0 = j & 1, j1 = (j >> 1) & 1, j2 = (j >> 2) & 1, j3 = (j >> 3) & 1;
                const int Jv = j0 | ((j1 ^ j0) << 1) | ((j2 ^ j1 ^ j0) << 2)
                             | ((j3 ^ j2 ^ j1 ^ j0) << 3);
                const int pj = j0 ^ j1 ^ j2 ^ j3;
                st[(pj ? pb1 : pb0) + 264 * (Jv ^ msk)] = v[j];
            }
            __syncthreads();
            #pragma unroll
            for (int j = 0; j < EPT; j++) v[j] = st[baseA + j];
        }
        // layer 1: ring permutation folded into expectation signs
    }

    // ---- expectations (ownership B) with permuted-sign Walsh combine ----
    float P = 0.f, g1 = 0.f, g3 = 0.f, g7 = 0.f, gF = 0.f;
    #pragma unroll
    for (int j = 0; j < EPT; j++) {
        float p = v[j] * v[j];
        P  += p;
        g1 += (__popc(j & 1)  & 1) ? -p : p;
        g3 += (__popc(j & 3)  & 1) ? -p : p;
        g7 += (__popc(j & 7)  & 1) ? -p : p;
        gF += (__popc(j & 15) & 1) ? -p : p;
    }
    const int pt  = __popc(tid) & 1;
    const int pt1 = __popc(tid >> 1) & 1;

    float acc[NQ];
    acc[0] = pt1 ? -gF : gF;
    #pragma unroll
    for (int q = 1; q < 8; q++) {
        int sq = __popc(tid & ((1 << (q + 1)) - 1)) & 1;
        acc[q] = sq ? -P : P;
    }
    acc[8]  = pt ? -g1 : g1;
    acc[9]  = pt ? -g3 : g3;
    acc[10] = pt ? -g7 : g7;
    acc[11] = pt ? -gF : gF;

    #pragma unroll
    for (int q = 0; q < NQ; q++) {
        #pragma unroll
        for (int off = 16; off; off >>= 1)
            acc[q] += __shfl_down_sync(0xFFFFFFFFu, acc[q], off);
    }
    const int w = tid >> 5;
    if (lane == 0) {
        #pragma unroll
        for (int q = 0; q < NQ; q++) red[w * NQ + q] = acc[q];
    }
    __syncthreads();
    if (tid < NQ) {
        float r = 0.0f;
        #pragma unroll
        for (int w2 = 0; w2 < THREADS / 32; w2++) r += red[w2 * NQ + tid];
        // deferred cosine scale: out *= (prod_{24 gates} cos)^2
        float cs = cosv[0];
        #pragma unroll
        for (int k = 1; k < 2 * NQ; k++) cs *= cosv[k];
        out[b * NQ + tid] = r * cs * cs;
    }
}

extern "C" void kernel_launch(void* const* d_in, const int* in_sizes, int n_in,
                              void* d_out, int out_size)
{
    const float* x  = (const float*)d_in[0];   // (1024, 12) float32
    const float* th = (const float*)d_in[1];   // (2, 12)    float32
    float* o = (float*)d_out;                  // (1024, 12) float32
    (void)in_sizes; (void)n_in; (void)out_size;
    qc_kernel<<<1024, THREADS>>>(x, th, o);
}

// round 14
// speedup vs baseline: 1.0253x; 1.0253x over previous
#include <cuda_runtime.h>

#define NQ      12
#define THREADS 256
#define NREG    8           // ull (amplitude pairs) per thread: 2048/256
#define STSZ    2176        // padded pair slots: max P(2047)=2174
typedef unsigned long long ull;

#define SGN2 0x8000000080000000ULL

__device__ __forceinline__ ull pk(float lo, float hi) {
    ull r; asm("mov.b64 %0, {%1, %2};" : "=l"(r) : "f"(lo), "f"(hi)); return r;
}
__device__ __forceinline__ void upk(ull a, float& lo, float& hi) {
    asm("mov.b64 {%0, %1}, %2;" : "=f"(lo), "=f"(hi) : "l"(a));
}
__device__ __forceinline__ ull fma2(ull a, ull b, ull c) {
    ull d; asm("fma.rn.f32x2 %0, %1, %2, %3;" : "=l"(d) : "l"(a), "l"(b), "l"(c)); return d;
}
__device__ __forceinline__ ull mul2(ull a, ull b) {
    ull d; asm("mul.rn.f32x2 %0, %1, %2;" : "=l"(d) : "l"(a), "l"(b)); return d;
}

// cross-register tan-form butterfly on register bit rb with packed coeff t2
#define XGATE(T2, RB)                                                       \
    {                                                                       \
        const ull t2  = (T2);                                               \
        const ull nt2 = t2 ^ SGN2;                                          \
        _Pragma("unroll")                                                   \
        for (int m = 0; m < 4; m++) {                                       \
            const int low = (1 << (RB)) - 1;                                \
            const int j0_ = ((m & ~low) << 1) | (m & low);                  \
            const int j1_ = j0_ | (1 << (RB));                              \
            ull a0 = v[j0_];                                                \
            v[j0_] = fma2(nt2, v[j1_], a0);                                 \
            v[j1_] = fma2(t2,  a0,   v[j1_]);                               \
        }                                                                   \
    }

__global__ __launch_bounds__(THREADS, 6)
void qc_kernel(const float* __restrict__ x,
               const float* __restrict__ th,
               float* __restrict__ out)
{
    __shared__ ull st2[STSZ];
    __shared__ float enc_c[NQ], enc_s[NQ];
    __shared__ ull th_t2[2][NQ];            // packed (tan, tan)
    __shared__ float cosv[2 * NQ];
    __shared__ float red[(THREADS / 32) * NQ];

    float* stf = (float*)st2;               // float view for the scatter

    const int b    = blockIdx.x;
    const int t    = threadIdx.x;
    const int lane = t & 31;

    // ownership bases (ull slots); pad P(p) = p + (p>>4); all four conflict-free
    const int baseA = 8 * t + (t >> 1);                                   // + j
    const int baseC = (t & 7) + 68 * ((t >> 4) & 1) + 136 * ((t >> 3) & 1)
                    + 272 * (t >> 5);                                     // + 8j + (j>>1)
    const int baseB = (t & 63) + ((t & 63) >> 4) + 544 * (t >> 6);        // + 68j
    const int baseD = t + (t >> 4);                                       // + 272j

    // ---- angle precompute ----
    if (t < NQ) {
        float s_, c_;
        sincosf(0.5f * x[b * NQ + t], &s_, &c_);
        enc_c[t] = c_; enc_s[t] = s_;
    } else if (t >= 32 && t < 32 + 2 * NQ) {
        int k = t - 32;
        float s_, c_;
        sincosf(0.5f * th[k], &s_, &c_);
        float tg = s_ / c_;
        th_t2[k / NQ][k % NQ] = pk(tg, tg);
        cosv[k] = c_;
    }
    __syncthreads();

    // ---- product state in A-ownership: pair p = 8t + j; halves = qubit 0 ----
    // p bits 0-2 = j -> qubits 1-3 ; p bits 3-10 = t -> qubits 4-11
    ull v[NREG];
    {
        float ht = (t & 1) ? enc_s[4] : enc_c[4];
        #pragma unroll
        for (int i = 1; i < 8; i++)
            ht *= ((t >> i) & 1) ? enc_s[4 + i] : enc_c[4 + i];
        ull hcs = pk(ht * enc_c[0], ht * enc_s[0]);
        float g01[4];
        #pragma unroll
        for (int m = 0; m < 4; m++)
            g01[m] = ((m & 1) ? enc_s[1] : enc_c[1]) * ((m & 2) ? enc_s[2] : enc_c[2]);
        #pragma unroll
        for (int j = 0; j < NREG; j++) {
            float jf = g01[j & 3] * ((j & 4) ? enc_s[3] : enc_c[3]);
            v[j] = mul2(hcs, pk(jf, jf));
        }
    }

    // scatter / sign constants (prefix-xor over t's 8 bits)
    unsigned yt = (unsigned)t; yt ^= yt << 1; yt ^= yt << 2; yt ^= yt << 4;
    const int pt = (yt >> 7) & 1;             // parity(t)
    // FIX: include p itself — d0 = p ^ correction. t-part folded here:
    const int Zt = t ^ (int)((yt << 1) & 0x1FE) ^ (pt << 9) ^ (pt << 10);

    // ---- variational layers (tan-form, cosines deferred) ----
    #pragma unroll
    for (int layer = 0; layer < 2; layer++) {
        const ull* T = th_t2[layer];

        // A-ownership: qubit 0 = register halves (scalar), qubits 1-3 = reg bits
        {
            float tg, dum; upk(T[0], tg, dum);
            #pragma unroll
            for (int j = 0; j < NREG; j++) {
                float lo, hi; upk(v[j], lo, hi);
                float nlo = fmaf(-tg, hi, lo);
                float nhi = fmaf( tg, lo, hi);
                v[j] = pk(nlo, nhi);
            }
        }
        XGATE(T[1], 0) XGATE(T[2], 1) XGATE(T[3], 2)

        #pragma unroll
        for (int j = 0; j < NREG; j++) st2[baseA + j] = v[j];
        __syncthreads();
        #pragma unroll
        for (int j = 0; j < NREG; j++) v[j] = st2[baseC + 8 * j + (j >> 1)];

        XGATE(T[4], 0) XGATE(T[5], 1) XGATE(T[6], 2)   // qubits 4-6

        #pragma unroll
        for (int j = 0; j < NREG; j++) st2[baseC + 8 * j + (j >> 1)] = v[j];
        __syncthreads();
        #pragma unroll
        for (int j = 0; j < NREG; j++) v[j] = st2[baseB + 68 * j];

        XGATE(T[7], 0) XGATE(T[8], 1) XGATE(T[9], 2)   // qubits 7-9

        #pragma unroll
        for (int j = 0; j < NREG; j++) st2[baseB + 68 * j] = v[j];
        __syncthreads();
        #pragma unroll
        for (int j = 0; j < NREG; j++) v[j] = st2[baseD + 272 * j];

        XGATE(T[10], 1) XGATE(T[11], 2)                // qubits 10-11 (j bit0 = q9, done)

        if (layer == 0) {
            // CNOT ring in pair space: d0 = p ^ correction (h=0), d1 = d0 ^ 0x7FF,
            // both halves land at half position pt ^ parity(j)
            __syncthreads();                           // all D reads done
            #pragma unroll
            for (int j = 0; j < NREG; j++) {
                const int j0 = j & 1, j1 = (j >> 1) & 1, j2 = (j >> 2) & 1;
                // FIX: fold j-part of p (j<<8) into the destination
                const int Cj = (j << 8) ^ (j0 << 9) ^ ((j0 ^ j1) << 10);
                const int pj = j0 ^ j1 ^ j2;
                int d0 = Zt ^ Cj;
                int d1 = d0 ^ 0x7FF;
                int hp = pt ^ pj;
                float lo, hi; upk(v[j], lo, hi);
                stf[2 * (d0 + (d0 >> 4)) + hp] = lo;
                stf[2 * (d1 + (d1 >> 4)) + hp] = hi;
            }
            __syncthreads();
            #pragma unroll
            for (int j = 0; j < NREG; j++) v[j] = st2[baseA + j];
        }
        // layer 1: trailing ring folded into expectation signs
    }

    // ---- expectations in D-ownership (p = t + 256j, halves = qubit 0) ----
    // bit_q(P(s)):  q=0 -> pT ^ pj                (no h)
    //               q=1..8 -> h ^ parity(t & ((1<<q)-1))
    //               q=9  -> h ^ pT ^ j0
    //               q=10 -> h ^ pT ^ j0 ^ j1
    //               q=11 -> h ^ pT ^ j0 ^ j1 ^ j2
    float Tacc = 0.f, D = 0.f, S1 = 0.f, S3 = 0.f, S7 = 0.f;
    #pragma unroll
    for (int j = 0; j < NREG; j++) {
        float lo, hi; upk(v[j], lo, hi);
        float l2 = lo * lo, h2 = hi * hi;
        float sum = l2 + h2, dif = l2 - h2;
        int pj = __popc(j) & 1;
        Tacc += pj ? -sum : sum;
        D    += dif;
        S1   += (j & 1) ? -dif : dif;
        S3   += (__popc(j & 3) & 1) ? -dif : dif;
        S7   += pj ? -dif : dif;
    }

    float acc[NQ];
    acc[0] = pt ? -Tacc : Tacc;
    #pragma unroll
    for (int q = 1; q < 9; q++) {
        int c = __popc(t & ((1 << q) - 1)) & 1;      // FIX: mask (1<<q)-1
        acc[q] = c ? -D : D;
    }
    acc[9]  = pt ? -S1 : S1;                          // FIX: shifted sign sets
    acc[10] = pt ? -S3 : S3;
    acc[11] = pt ? -S7 : S7;

    #pragma unroll
    for (int q = 0; q < NQ; q++) {
        #pragma unroll
        for (int off = 16; off; off >>= 1)
            acc[q] += __shfl_down_sync(0xFFFFFFFFu, acc[q], off);
    }
    const int w = t >> 5;
    if (lane == 0) {
        #pragma unroll
        for (int q = 0; q < NQ; q++) red[w * NQ + q] = acc[q];
    }
    __syncthreads();
    if (t < NQ) {
        float r = 0.0f;
        #pragma unroll
        for (int w2 = 0; w2 < THREADS / 32; w2++) r += red[w2 * NQ + t];
        float cs = cosv[0];
        #pragma unroll
        for (int k = 1; k < 2 * NQ; k++) cs *= cosv[k];
        out[b * NQ + t] = r * cs * cs;
    }
}

extern "C" void kernel_launch(void* const* d_in, const int* in_sizes, int n_in,
                              void* d_out, int out_size)
{
    const float* x  = (const float*)d_in[0];   // (1024, 12) float32
    const float* th = (const float*)d_in[1];   // (2, 12)    float32
    float* o = (float*)d_out;                  // (1024, 12) float32
    (void)in_sizes; (void)n_in; (void)out_size;
    qc_kernel<<<1024, THREADS>>>(x, th, o);
}